// round 3
// baseline (speedup 1.0000x reference)
#include <cuda_runtime.h>
#include <math.h>

#define B_    2
#define S_    2048
#define D_    768
#define H_    12
#define DEP_  64
#define BH_   (B_*H_)            // 24
#define MROWS (B_*S_)            // 4096
#define OUT_ELEMS (B_*S_*D_)     // 3145728
#define ATTN_ELEMS (BH_*S_*S_)   // 100663296

// ---- scratch (alloc-free, __device__ globals) ----
__device__ float g_Qp[BH_*S_*DEP_];
__device__ float g_Kp[BH_*S_*DEP_];
__device__ float g_Vp[BH_*S_*DEP_];
__device__ float g_ctx[MROWS*D_];
__device__ float g_attn_scratch[ATTN_ELEMS];  // used only if d_out lacks attn

__device__ __forceinline__ float neg_inf() { return __int_as_float(0xff800000); }

// ======================================================================
// C[M,N] = alpha * (X[M,K] @ W[N,K]^T + bias[N])
// head_split: write C as [B,H,S,DEP] instead of [M,N]
// 64x64 block tile, BK=16, 256 threads, 4x4 microtile,
// software-pipelined global->reg prefetch.
// ======================================================================
__global__ __launch_bounds__(256)
void gemm_xwT_kernel(const float* __restrict__ X,
                     const float* __restrict__ W,
                     const float* __restrict__ bias,
                     float* __restrict__ C,
                     int M, int N, int K,
                     float alpha, int head_split)
{
    __shared__ float Xs[16][68];
    __shared__ float Ws[16][68];

    const int t  = threadIdx.x;
    const int tx = t & 15, ty = t >> 4;
    const int n0 = blockIdx.x * 64;
    const int m0 = blockIdx.y * 64;

    const int lr  = t >> 2;   // 0..63 (tile row)
    const int lk4 = t & 3;    // 0..3  (k-offset group)

    const float* Xp = X + (size_t)(m0 + lr) * K + lk4 * 4;
    const float* Wp = W + (size_t)(n0 + lr) * K + lk4 * 4;

    float acc[4][4] = {};

    float4 xv = *(const float4*)(Xp);
    float4 wv = *(const float4*)(Wp);

    for (int k0 = 0; k0 < K; k0 += 16) {
        Xs[lk4*4+0][lr] = xv.x; Xs[lk4*4+1][lr] = xv.y;
        Xs[lk4*4+2][lr] = xv.z; Xs[lk4*4+3][lr] = xv.w;
        Ws[lk4*4+0][lr] = wv.x; Ws[lk4*4+1][lr] = wv.y;
        Ws[lk4*4+2][lr] = wv.z; Ws[lk4*4+3][lr] = wv.w;
        __syncthreads();

        if (k0 + 16 < K) {                 // prefetch next slab into registers
            xv = *(const float4*)(Xp + k0 + 16);
            wv = *(const float4*)(Wp + k0 + 16);
        }

#pragma unroll
        for (int kk = 0; kk < 16; kk++) {
            float4 a = *(const float4*)&Xs[kk][ty*4];
            float4 b = *(const float4*)&Ws[kk][tx*4];
            float av[4] = {a.x, a.y, a.z, a.w};
            float bv[4] = {b.x, b.y, b.z, b.w};
#pragma unroll
            for (int i = 0; i < 4; i++)
#pragma unroll
                for (int j = 0; j < 4; j++)
                    acc[i][j] += av[i] * bv[j];
        }
        __syncthreads();
    }

#pragma unroll
    for (int i = 0; i < 4; i++) {
        const int m = m0 + ty*4 + i;
#pragma unroll
        for (int j = 0; j < 4; j++) {
            const int n = n0 + tx*4 + j;
            const float v = alpha * (acc[i][j] + bias[n]);
            if (head_split) {
                const int b = m / S_, s = m % S_;
                const int h = n / DEP_, dd = n % DEP_;
                C[(((size_t)(b*H_ + h))*S_ + s)*DEP_ + dd] = v;
            } else {
                C[(size_t)m * N + n] = v;
            }
        }
    }
}

// ======================================================================
// logits[bh, m, n] = sum_k Qp[bh,m,k]*Kp[bh,n,k]   (Q pre-scaled by 1/8)
// masked with -inf where mask[b, n] == 0
// grid: (S/64, S/64, B*H)
// ======================================================================
__global__ __launch_bounds__(256)
void logits_kernel(const float* __restrict__ Qp,
                   const float* __restrict__ Kp,
                   const int*   __restrict__ mask,
                   float* __restrict__ attn)
{
    __shared__ float Qs[64][68];  // [k][m]
    __shared__ float Ks[64][68];  // [k][n]

    const int t  = threadIdx.x;
    const int tx = t & 15, ty = t >> 4;
    const int n0 = blockIdx.x * 64;
    const int m0 = blockIdx.y * 64;
    const int bh = blockIdx.z;
    const int b  = bh / H_;

    const float* Qb = Qp + ((size_t)bh * S_ + m0) * DEP_;
    const float* Kb = Kp + ((size_t)bh * S_ + n0) * DEP_;

#pragma unroll
    for (int i = 0; i < 4; i++) {
        const int idx = t + i * 256;
        const int r = idx >> 4, c4 = idx & 15;
        float4 qv = *(const float4*)(Qb + r * DEP_ + c4 * 4);
        float4 kv = *(const float4*)(Kb + r * DEP_ + c4 * 4);
        Qs[c4*4+0][r] = qv.x; Qs[c4*4+1][r] = qv.y;
        Qs[c4*4+2][r] = qv.z; Qs[c4*4+3][r] = qv.w;
        Ks[c4*4+0][r] = kv.x; Ks[c4*4+1][r] = kv.y;
        Ks[c4*4+2][r] = kv.z; Ks[c4*4+3][r] = kv.w;
    }
    __syncthreads();

    float acc[4][4] = {};
#pragma unroll
    for (int kk = 0; kk < 64; kk++) {
        float4 a = *(const float4*)&Qs[kk][ty*4];
        float4 bb = *(const float4*)&Ks[kk][tx*4];
        float av[4] = {a.x, a.y, a.z, a.w};
        float bv[4] = {bb.x, bb.y, bb.z, bb.w};
#pragma unroll
        for (int i = 0; i < 4; i++)
#pragma unroll
            for (int j = 0; j < 4; j++)
                acc[i][j] += av[i] * bv[j];
    }

    const int* mrow = mask + b * S_;
    float* Cb = attn + (size_t)bh * S_ * S_;
    float msel[4];
#pragma unroll
    for (int j = 0; j < 4; j++)
        msel[j] = (mrow[n0 + tx*4 + j] == 0) ? 1.0f : 0.0f;

#pragma unroll
    for (int i = 0; i < 4; i++) {
        const int m = m0 + ty*4 + i;
        float vals[4];
#pragma unroll
        for (int j = 0; j < 4; j++)
            vals[j] = (msel[j] != 0.0f) ? neg_inf() : acc[i][j];
        *(float4*)(Cb + (size_t)m * S_ + n0 + tx*4) =
            make_float4(vals[0], vals[1], vals[2], vals[3]);
    }
}

// ======================================================================
// In-place row softmax over rows of length S_ (one block per row)
// ======================================================================
__global__ __launch_bounds__(256)
void softmax_kernel(float* __restrict__ attn)
{
    float* p = attn + (size_t)blockIdx.x * S_;
    const int t = threadIdx.x;

    float x[8];
    float mx = neg_inf();
#pragma unroll
    for (int i = 0; i < 8; i++) { x[i] = p[t + i*256]; mx = fmaxf(mx, x[i]); }

    __shared__ float redmax[8];
    __shared__ float redsum[8];

#pragma unroll
    for (int o = 16; o > 0; o >>= 1)
        mx = fmaxf(mx, __shfl_xor_sync(0xffffffffu, mx, o));
    if ((t & 31) == 0) redmax[t >> 5] = mx;
    __syncthreads();
    float bm = redmax[0];
#pragma unroll
    for (int i = 1; i < 8; i++) bm = fmaxf(bm, redmax[i]);

    float s = 0.0f;
#pragma unroll
    for (int i = 0; i < 8; i++) { x[i] = expf(x[i] - bm); s += x[i]; }
#pragma unroll
    for (int o = 16; o > 0; o >>= 1)
        s += __shfl_xor_sync(0xffffffffu, s, o);
    if ((t & 31) == 0) redsum[t >> 5] = s;
    __syncthreads();
    float tot = 0.0f;
#pragma unroll
    for (int i = 0; i < 8; i++) tot += redsum[i];
    const float inv = 1.0f / tot;

#pragma unroll
    for (int i = 0; i < 8; i++) p[t + i*256] = x[i] * inv;
}

// ======================================================================
// ctx[b, s, h*64+d] = sum_n attn[bh, s, n] * Vp[bh, n, d]
// grid: (S/64, B*H)
// ======================================================================
__global__ __launch_bounds__(256)
void ctx_kernel(const float* __restrict__ attn,
                const float* __restrict__ Vp,
                float* __restrict__ ctx)
{
    __shared__ float As[64][68];  // [n][m]
    __shared__ float Vs[64][68];  // [n][d]

    const int t  = threadIdx.x;
    const int tx = t & 15, ty = t >> 4;
    const int m0 = blockIdx.x * 64;
    const int bh = blockIdx.y;
    const int b  = bh / H_, h = bh % H_;

    const float* Ab = attn + (size_t)bh * S_ * S_;
    const float* Vb = Vp   + (size_t)bh * S_ * DEP_;

    float acc[4][4] = {};
    for (int n0 = 0; n0 < S_; n0 += 64) {
#pragma unroll
        for (int i = 0; i < 4; i++) {
            const int idx = t + i * 256;
            const int r = idx >> 4, c4 = idx & 15;
            float4 av = *(const float4*)(Ab + (size_t)(m0 + r) * S_ + n0 + c4*4);
            As[c4*4+0][r] = av.x; As[c4*4+1][r] = av.y;
            As[c4*4+2][r] = av.z; As[c4*4+3][r] = av.w;
            float4 vv = *(const float4*)(Vb + (size_t)(n0 + r) * DEP_ + c4*4);
            *(float4*)&Vs[r][c4*4] = vv;
        }
        __syncthreads();
#pragma unroll
        for (int nn = 0; nn < 64; nn++) {
            float4 a = *(const float4*)&As[nn][ty*4];   // m components
            float4 v = *(const float4*)&Vs[nn][tx*4];   // d components
            float av[4] = {a.x, a.y, a.z, a.w};
            float vv[4] = {v.x, v.y, v.z, v.w};
#pragma unroll
            for (int i = 0; i < 4; i++)
#pragma unroll
                for (int j = 0; j < 4; j++)
                    acc[i][j] += av[i] * vv[j];
        }
        __syncthreads();
    }

#pragma unroll
    for (int i = 0; i < 4; i++) {
        const int m = m0 + ty*4 + i;
        float* dst = ctx + ((size_t)b * S_ + m) * D_ + h * DEP_ + tx*4;
        *(float4*)dst = make_float4(acc[i][0], acc[i][1], acc[i][2], acc[i][3]);
    }
}

// ======================================================================
extern "C" void kernel_launch(void* const* d_in, const int* in_sizes, int n_in,
                              void* d_out, int out_size)
{
    const float* q    = (const float*)d_in[0];
    const float* k    = (const float*)d_in[1];
    const float* v    = (const float*)d_in[2];
    const int*   mask = (const int*)  d_in[3];
    const float* wq_w = (const float*)d_in[4];
    const float* wq_b = (const float*)d_in[5];
    const float* wk_w = (const float*)d_in[6];
    const float* wk_b = (const float*)d_in[7];
    const float* wv_w = (const float*)d_in[8];
    const float* wv_b = (const float*)d_in[9];
    const float* wo_w = (const float*)d_in[10];
    const float* wo_b = (const float*)d_in[11];
    float* out = (float*)d_out;

    float *Qp, *Kp, *Vp, *ctxp, *attn_s;
    cudaGetSymbolAddress((void**)&Qp,     g_Qp);
    cudaGetSymbolAddress((void**)&Kp,     g_Kp);
    cudaGetSymbolAddress((void**)&Vp,     g_Vp);
    cudaGetSymbolAddress((void**)&ctxp,   g_ctx);
    cudaGetSymbolAddress((void**)&attn_s, g_attn_scratch);

    // If d_out holds (out, attn) flattened in tuple order, write attn there
    // directly; otherwise keep it in device scratch.
    const long long need = (long long)OUT_ELEMS + (long long)ATTN_ELEMS;
    float* attn = ((long long)out_size >= need) ? (out + OUT_ELEMS) : attn_s;

    // Q/K/V projections (Q pre-scaled by 1/sqrt(64) = 0.125)
    gemm_xwT_kernel<<<dim3(D_/64, MROWS/64), 256>>>(q, wq_w, wq_b, Qp,
                                                    MROWS, D_, D_, 0.125f, 1);
    gemm_xwT_kernel<<<dim3(D_/64, MROWS/64), 256>>>(k, wk_w, wk_b, Kp,
                                                    MROWS, D_, D_, 1.0f, 1);
    gemm_xwT_kernel<<<dim3(D_/64, MROWS/64), 256>>>(v, wv_w, wv_b, Vp,
                                                    MROWS, D_, D_, 1.0f, 1);

    // raw logits (masked)
    logits_kernel<<<dim3(S_/64, S_/64, BH_), 256>>>(Qp, Kp, mask, attn);

    // in-place softmax -> final attn probabilities
    softmax_kernel<<<dim3(BH_ * S_), 256>>>(attn);

    // ctx = attn @ V, written in merged-head [B,S,D] layout
    ctx_kernel<<<dim3(S_/64, BH_), 256>>>(attn, Vp, ctxp);

    // output projection
    gemm_xwT_kernel<<<dim3(D_/64, MROWS/64), 256>>>(ctxp, wo_w, wo_b, out,
                                                    MROWS, D_, D_, 1.0f, 0);
}

// round 4
// speedup vs baseline: 1.0378x; 1.0378x over previous
#include <cuda_runtime.h>
#include <math.h>

#define B_    2
#define S_    2048
#define D_    768
#define H_    12
#define DEP_  64
#define BH_   (B_*H_)            // 24
#define MROWS (B_*S_)            // 4096
#define OUT_ELEMS (B_*S_*D_)     // 3145728
#define ATTN_ELEMS (BH_*S_*S_)   // 100663296

// ---- scratch (alloc-free, __device__ globals) ----
__device__ float g_Qp[BH_*S_*DEP_];
__device__ float g_Kp[BH_*S_*DEP_];
__device__ float g_Vp[BH_*S_*DEP_];
__device__ float g_ctx[MROWS*D_];
__device__ float g_rowmax[BH_*S_];
__device__ float g_rowinv[BH_*S_];
__device__ float g_attn_scratch[ATTN_ELEMS];  // used only if d_out lacks attn

__device__ __forceinline__ float neg_inf() { return __int_as_float(0xff800000); }

// ======================================================================
// C[M,N] = alpha * (X[M,K] @ W[N,K]^T + bias[N])
// block tile 128(m) x 64(n), BK=16, 256 threads, 8x4 microtile,
// register-prefetch pipelined. head_split: write [B,H,S,DEP] layout.
// Requires n-tile (64) aligned to head boundary (DEP_=64). K%16==0.
// ======================================================================
__global__ __launch_bounds__(256)
void gemm_xwT_kernel(const float* __restrict__ X,
                     const float* __restrict__ W,
                     const float* __restrict__ bias,
                     float* __restrict__ C,
                     int K, int N, float alpha, int head_split)
{
    __shared__ float Xs[16][132];
    __shared__ float Ws[16][68];

    const int t  = threadIdx.x;
    const int tx = t & 15;        // n: tx*4
    const int ty = t >> 4;        // m: ty*8
    const int n0 = blockIdx.x * 64;
    const int m0 = blockIdx.y * 128;

    // loader mapping
    const int lr = t >> 2;        // 0..63
    const int lc = t & 3;         // k-group

    const float* Xr0 = X + (size_t)(m0 + lr) * K + lc * 4;        // rows 0..63
    const float* Xr1 = Xr0 + (size_t)64 * K;                      // rows 64..127
    const float* Wr  = W + (size_t)(n0 + lr) * K + lc * 4;        // 64 n-rows

    float acc[8][4] = {};

    float4 x0 = *(const float4*)(Xr0);
    float4 x1 = *(const float4*)(Xr1);
    float4 w0 = *(const float4*)(Wr);

    for (int k0 = 0; k0 < K; k0 += 16) {
        Xs[lc*4+0][lr]    = x0.x; Xs[lc*4+1][lr]    = x0.y;
        Xs[lc*4+2][lr]    = x0.z; Xs[lc*4+3][lr]    = x0.w;
        Xs[lc*4+0][64+lr] = x1.x; Xs[lc*4+1][64+lr] = x1.y;
        Xs[lc*4+2][64+lr] = x1.z; Xs[lc*4+3][64+lr] = x1.w;
        Ws[lc*4+0][lr]    = w0.x; Ws[lc*4+1][lr]    = w0.y;
        Ws[lc*4+2][lr]    = w0.z; Ws[lc*4+3][lr]    = w0.w;
        __syncthreads();

        if (k0 + 16 < K) {
            x0 = *(const float4*)(Xr0 + k0 + 16);
            x1 = *(const float4*)(Xr1 + k0 + 16);
            w0 = *(const float4*)(Wr  + k0 + 16);
        }

#pragma unroll
        for (int kk = 0; kk < 16; kk++) {
            float4 a0 = *(const float4*)&Xs[kk][ty*8];
            float4 a1 = *(const float4*)&Xs[kk][ty*8+4];
            float4 bv = *(const float4*)&Ws[kk][tx*4];
            float av[8] = {a0.x,a0.y,a0.z,a0.w,a1.x,a1.y,a1.z,a1.w};
            float b4[4] = {bv.x,bv.y,bv.z,bv.w};
#pragma unroll
            for (int i = 0; i < 8; i++)
#pragma unroll
                for (int j = 0; j < 4; j++)
                    acc[i][j] += av[i] * b4[j];
        }
        __syncthreads();
    }

    const float4 bias4 = *(const float4*)(bias + n0 + tx*4);
#pragma unroll
    for (int i = 0; i < 8; i++) {
        const int m = m0 + ty*8 + i;
        float4 r;
        r.x = alpha * (acc[i][0] + bias4.x);
        r.y = alpha * (acc[i][1] + bias4.y);
        r.z = alpha * (acc[i][2] + bias4.z);
        r.w = alpha * (acc[i][3] + bias4.w);
        if (head_split) {
            const int b = m / S_, s = m % S_;
            const int h = n0 / DEP_;
            *(float4*)(C + (((size_t)(b*H_ + h))*S_ + s)*DEP_ + tx*4) = r;
        } else {
            *(float4*)(C + (size_t)m * N + n0 + tx*4) = r;
        }
    }
}

// ======================================================================
// logits[bh, m, n] = sum_k Qp[bh,m,k]*Kp[bh,n,k]  (Q pre-scaled by 1/8)
// masked with -inf where mask[b, n] == 0.
// 128x128 tile, 256 threads, 8x8 microtile. grid: (16, 16, 24)
// ======================================================================
__global__ __launch_bounds__(256)
void logits_kernel(const float* __restrict__ Qp,
                   const float* __restrict__ Kp,
                   const int*   __restrict__ mask,
                   float* __restrict__ attn)
{
    __shared__ float Qs[16][132];
    __shared__ float Ks[16][132];

    const int t  = threadIdx.x;
    const int tx = t & 15;        // n: tx*8
    const int ty = t >> 4;        // m: ty*8
    const int n0 = blockIdx.x * 128;
    const int m0 = blockIdx.y * 128;
    const int bh = blockIdx.z;
    const int b  = bh / H_;

    const float* Qb = Qp + ((size_t)bh * S_ + m0) * DEP_;
    const float* Kb = Kp + ((size_t)bh * S_ + n0) * DEP_;

    // loader mapping: 2 float4 per matrix per chunk
    const int lr0 = t >> 2;           // 0..63
    const int lc  = t & 3;

    const float* Qr0 = Qb + (size_t)lr0 * DEP_ + lc*4;
    const float* Qr1 = Qr0 + (size_t)64 * DEP_;
    const float* Kr0 = Kb + (size_t)lr0 * DEP_ + lc*4;
    const float* Kr1 = Kr0 + (size_t)64 * DEP_;

    float acc[8][8] = {};

    float4 q0 = *(const float4*)(Qr0);
    float4 q1 = *(const float4*)(Qr1);
    float4 k0v = *(const float4*)(Kr0);
    float4 k1v = *(const float4*)(Kr1);

    for (int k0 = 0; k0 < DEP_; k0 += 16) {
        Qs[lc*4+0][lr0]    = q0.x; Qs[lc*4+1][lr0]    = q0.y;
        Qs[lc*4+2][lr0]    = q0.z; Qs[lc*4+3][lr0]    = q0.w;
        Qs[lc*4+0][64+lr0] = q1.x; Qs[lc*4+1][64+lr0] = q1.y;
        Qs[lc*4+2][64+lr0] = q1.z; Qs[lc*4+3][64+lr0] = q1.w;
        Ks[lc*4+0][lr0]    = k0v.x; Ks[lc*4+1][lr0]    = k0v.y;
        Ks[lc*4+2][lr0]    = k0v.z; Ks[lc*4+3][lr0]    = k0v.w;
        Ks[lc*4+0][64+lr0] = k1v.x; Ks[lc*4+1][64+lr0] = k1v.y;
        Ks[lc*4+2][64+lr0] = k1v.z; Ks[lc*4+3][64+lr0] = k1v.w;
        __syncthreads();

        if (k0 + 16 < DEP_) {
            q0  = *(const float4*)(Qr0 + k0 + 16);
            q1  = *(const float4*)(Qr1 + k0 + 16);
            k0v = *(const float4*)(Kr0 + k0 + 16);
            k1v = *(const float4*)(Kr1 + k0 + 16);
        }

#pragma unroll
        for (int kk = 0; kk < 16; kk++) {
            float4 a0 = *(const float4*)&Qs[kk][ty*8];
            float4 a1 = *(const float4*)&Qs[kk][ty*8+4];
            float4 b0 = *(const float4*)&Ks[kk][tx*8];
            float4 b1 = *(const float4*)&Ks[kk][tx*8+4];
            float av[8] = {a0.x,a0.y,a0.z,a0.w,a1.x,a1.y,a1.z,a1.w};
            float bv[8] = {b0.x,b0.y,b0.z,b0.w,b1.x,b1.y,b1.z,b1.w};
#pragma unroll
            for (int i = 0; i < 8; i++)
#pragma unroll
                for (int j = 0; j < 8; j++)
                    acc[i][j] += av[i] * bv[j];
        }
        __syncthreads();
    }

    const int* mrow = mask + b * S_;
    bool mz[8];
#pragma unroll
    for (int j = 0; j < 8; j++)
        mz[j] = (mrow[n0 + tx*8 + j] == 0);

    float* Cb = attn + (size_t)bh * S_ * S_;
#pragma unroll
    for (int i = 0; i < 8; i++) {
        const int m = m0 + ty*8 + i;
        float v[8];
#pragma unroll
        for (int j = 0; j < 8; j++)
            v[j] = mz[j] ? neg_inf() : acc[i][j];
        float* dst = Cb + (size_t)m * S_ + n0 + tx*8;
        *(float4*)(dst)     = make_float4(v[0], v[1], v[2], v[3]);
        *(float4*)(dst + 4) = make_float4(v[4], v[5], v[6], v[7]);
    }
}

// ======================================================================
// Row stats over raw logits: gmax[row] = max, ginv[row] = 1/sum(exp(x-max))
// One block per row.
// ======================================================================
__global__ __launch_bounds__(256)
void row_stats_kernel(const float* __restrict__ attn,
                      float* __restrict__ gmax,
                      float* __restrict__ ginv)
{
    const float* p = attn + (size_t)blockIdx.x * S_;
    const int t = threadIdx.x;

    float x[8];
    float mx = neg_inf();
#pragma unroll
    for (int i = 0; i < 8; i++) { x[i] = p[t + i*256]; mx = fmaxf(mx, x[i]); }

    __shared__ float redm[8];
    __shared__ float reds[8];

#pragma unroll
    for (int o = 16; o > 0; o >>= 1)
        mx = fmaxf(mx, __shfl_xor_sync(0xffffffffu, mx, o));
    if ((t & 31) == 0) redm[t >> 5] = mx;
    __syncthreads();
    float bm = redm[0];
#pragma unroll
    for (int i = 1; i < 8; i++) bm = fmaxf(bm, redm[i]);

    float s = 0.0f;
#pragma unroll
    for (int i = 0; i < 8; i++) s += __expf(x[i] - bm);
#pragma unroll
    for (int o = 16; o > 0; o >>= 1)
        s += __shfl_xor_sync(0xffffffffu, s, o);
    if ((t & 31) == 0) reds[t >> 5] = s;
    __syncthreads();

    if (t == 0) {
        float tot = 0.0f;
#pragma unroll
        for (int i = 0; i < 8; i++) tot += reds[i];
        gmax[blockIdx.x] = bm;
        ginv[blockIdx.x] = 1.0f / tot;
    }
}

// ======================================================================
// ctx = softmax(logits) @ V, with on-the-fly normalization.
// Reads RAW logits from attn, computes p = exp(x - max)*inv, writes p back
// (final normalized attn output) and accumulates p @ V.
// Block: 128 rows(m) x 64 cols(d); n-chunks of 32. grid: (16, 24)
// ======================================================================
__global__ __launch_bounds__(256)
void ctx_kernel(float* __restrict__ attn,
                const float* __restrict__ Vp,
                const float* __restrict__ gmax,
                const float* __restrict__ ginv,
                float* __restrict__ ctx)
{
    __shared__ float As[32][132];   // [n][m] normalized probs
    __shared__ float Vs[32][68];    // [n][d]
    __shared__ float smax[128];
    __shared__ float sinv[128];

    const int t  = threadIdx.x;
    const int tx = t & 15;          // d: tx*4
    const int ty = t >> 4;          // m: ty*8
    const int m0 = blockIdx.x * 128;
    const int bh = blockIdx.y;
    const int b  = bh / H_, h = bh % H_;

    if (t < 128) {
        smax[t] = gmax[bh * S_ + m0 + t];
        sinv[t] = ginv[bh * S_ + m0 + t];
    }
    __syncthreads();

    float* Ab = attn + (size_t)bh * S_ * S_;
    const float* Vb = Vp + (size_t)bh * S_ * DEP_;

    float acc[8][4] = {};

    for (int nc = 0; nc < S_; nc += 32) {
        // load attn chunk, normalize, write back, transpose into smem
#pragma unroll
        for (int i = 0; i < 4; i++) {
            const int idx = t + i * 256;
            const int r = idx >> 3;          // 0..127 (m)
            const int c = idx & 7;           // n group
            float* gp = Ab + (size_t)(m0 + r) * S_ + nc + c*4;
            float4 x = *(const float4*)gp;
            const float mr = smax[r], ir = sinv[r];
            float4 pv;
            pv.x = __expf(x.x - mr) * ir;
            pv.y = __expf(x.y - mr) * ir;
            pv.z = __expf(x.z - mr) * ir;
            pv.w = __expf(x.w - mr) * ir;
            *(float4*)gp = pv;               // final attn output
            As[c*4+0][r] = pv.x; As[c*4+1][r] = pv.y;
            As[c*4+2][r] = pv.z; As[c*4+3][r] = pv.w;
        }
        // load V chunk
#pragma unroll
        for (int i = 0; i < 2; i++) {
            const int idx = t + i * 256;
            const int r = idx >> 4;          // 0..31 (n)
            const int c = idx & 15;          // d group
            *(float4*)&Vs[r][c*4] =
                *(const float4*)(Vb + (size_t)(nc + r) * DEP_ + c*4);
        }
        __syncthreads();

#pragma unroll
        for (int nn = 0; nn < 32; nn++) {
            float4 a0 = *(const float4*)&As[nn][ty*8];
            float4 a1 = *(const float4*)&As[nn][ty*8+4];
            float4 vv = *(const float4*)&Vs[nn][tx*4];
            float av[8] = {a0.x,a0.y,a0.z,a0.w,a1.x,a1.y,a1.z,a1.w};
            float v4[4] = {vv.x,vv.y,vv.z,vv.w};
#pragma unroll
            for (int i = 0; i < 8; i++)
#pragma unroll
                for (int j = 0; j < 4; j++)
                    acc[i][j] += av[i] * v4[j];
        }
        __syncthreads();
    }

#pragma unroll
    for (int i = 0; i < 8; i++) {
        const int m = m0 + ty*8 + i;
        float* dst = ctx + ((size_t)b * S_ + m) * D_ + h * DEP_ + tx*4;
        *(float4*)dst = make_float4(acc[i][0], acc[i][1], acc[i][2], acc[i][3]);
    }
}

// ======================================================================
extern "C" void kernel_launch(void* const* d_in, const int* in_sizes, int n_in,
                              void* d_out, int out_size)
{
    const float* q    = (const float*)d_in[0];
    const float* k    = (const float*)d_in[1];
    const float* v    = (const float*)d_in[2];
    const int*   mask = (const int*)  d_in[3];
    const float* wq_w = (const float*)d_in[4];
    const float* wq_b = (const float*)d_in[5];
    const float* wk_w = (const float*)d_in[6];
    const float* wk_b = (const float*)d_in[7];
    const float* wv_w = (const float*)d_in[8];
    const float* wv_b = (const float*)d_in[9];
    const float* wo_w = (const float*)d_in[10];
    const float* wo_b = (const float*)d_in[11];
    float* out = (float*)d_out;

    float *Qp, *Kp, *Vp, *ctxp, *rmax, *rinv, *attn_s;
    cudaGetSymbolAddress((void**)&Qp,     g_Qp);
    cudaGetSymbolAddress((void**)&Kp,     g_Kp);
    cudaGetSymbolAddress((void**)&Vp,     g_Vp);
    cudaGetSymbolAddress((void**)&ctxp,   g_ctx);
    cudaGetSymbolAddress((void**)&rmax,   g_rowmax);
    cudaGetSymbolAddress((void**)&rinv,   g_rowinv);
    cudaGetSymbolAddress((void**)&attn_s, g_attn_scratch);

    const long long need = (long long)OUT_ELEMS + (long long)ATTN_ELEMS;
    float* attn = ((long long)out_size >= need) ? (out + OUT_ELEMS) : attn_s;

    // Q/K/V projections (Q pre-scaled by 1/sqrt(64) = 0.125)
    dim3 pgrid(D_/64, MROWS/128);
    gemm_xwT_kernel<<<pgrid, 256>>>(q, wq_w, wq_b, Qp, D_, D_, 0.125f, 1);
    gemm_xwT_kernel<<<pgrid, 256>>>(k, wk_w, wk_b, Kp, D_, D_, 1.0f, 1);
    gemm_xwT_kernel<<<pgrid, 256>>>(v, wv_w, wv_b, Vp, D_, D_, 1.0f, 1);

    // raw masked logits
    logits_kernel<<<dim3(S_/128, S_/128, BH_), 256>>>(Qp, Kp, mask, attn);

    // per-row softmax stats (no attn rewrite)
    row_stats_kernel<<<dim3(BH_ * S_), 256>>>(attn, rmax, rinv);

    // ctx = softmax @ V; normalizes attn in place as it goes
    ctx_kernel<<<dim3(S_/128, BH_), 256>>>(attn, Vp, rmax, rinv, ctxp);

    // output projection
    gemm_xwT_kernel<<<pgrid, 256>>>(ctxp, wo_w, wo_b, out, D_, D_, 1.0f, 0);
}